// round 4
// baseline (speedup 1.0000x reference)
#include <cuda_runtime.h>
#include <cstdint>

#define K_TOP    30
#define EMB_DIM  128
#define NT       256

// Map float -> uint32 whose unsigned order matches float order (ascending).
__device__ __forceinline__ unsigned int float_to_sortable(float f) {
    unsigned int b = __float_as_uint(f);
    return (b & 0x80000000u) ? ~b : (b | 0x80000000u);
}

__device__ __forceinline__ unsigned long long shflx64(unsigned long long x, int m) {
    unsigned lo = (unsigned)x, hi = (unsigned)(x >> 32);
    lo = __shfl_xor_sync(0xffffffffu, lo, m);
    hi = __shfl_xor_sync(0xffffffffu, hi, m);
    return ((unsigned long long)hi << 32) | lo;
}

__device__ __forceinline__ unsigned long long cmpx(unsigned long long a,
                                                   unsigned long long b,
                                                   bool keep_max) {
    unsigned long long mx = a > b ? a : b;
    unsigned long long mn = a > b ? b : a;
    return keep_max ? mx : mn;
}

// 5-stage descending bitonic merge of a bitonic sequence held across the warp.
__device__ __forceinline__ unsigned long long warp_merge_desc(unsigned long long key,
                                                              int lane) {
    #pragma unroll
    for (int j = 16; j >= 1; j >>= 1) {
        bool lower = (lane & j) == 0;
        unsigned long long other = shflx64(key, j);
        key = cmpx(key, other, lower);
    }
    return key;
}

__global__ void __launch_bounds__(NT)
sortpool_kernel(const float* __restrict__ emb,
                const int*   __restrict__ sizes,
                float*       __restrict__ out,
                int G) {
    const int g    = blockIdx.x;
    const int tid  = threadIdx.x;
    const int lane = tid & 31;
    const int wid  = tid >> 5;

    __shared__ unsigned long long s[NT];
    __shared__ int wsum[NT / 32];
    __shared__ int sh_off;
    __shared__ int tops[32];

    // ---- offset = prefix sum of sizes[0..g-1], int4-vectorized (L2-resident) ----
    int acc = 0;
    {
        const int4* s4 = (const int4*)sizes;
        const int nfull = g >> 2;               // int4 groups fully below g
        for (int j = tid; j < nfull; j += NT) {
            int4 v = s4[j];
            acc += v.x + v.y + v.z + v.w;
        }
        if (tid < (g & 3)) acc += sizes[(nfull << 2) + tid];
    }
    #pragma unroll
    for (int m = 16; m; m >>= 1) acc += __shfl_xor_sync(0xffffffffu, acc, m);
    if (lane == 0) wsum[wid] = acc;
    __syncthreads();
    if (tid == 0) {
        int o = 0;
        #pragma unroll
        for (int w = 0; w < NT / 32; w++) o += wsum[w];
        sh_off = o;
    }
    __syncthreads();
    const int offset = sh_off;
    const int size   = sizes[g];
    const int nwarps = (size + 31) >> 5;   // warps holding real data

    unsigned long long key = (unsigned long long)(unsigned int)(~(unsigned int)tid);

    if (wid < nwarps) {
        // ---- composite key: (sortable(val) << 32) | ~local_idx ----
        // Descending composite order == descending value, ascending index on ties.
        if (tid < size) {
            float v = __ldg(&emb[(size_t)(offset + tid) * EMB_DIM + (EMB_DIM - 1)]);
            key = ((unsigned long long)float_to_sortable(v) << 32)
                  | (unsigned int)(~(unsigned int)tid);
        }
        // ---- warp-local descending bitonic sort of 32 keys ----
        #pragma unroll
        for (int k = 2; k <= 16; k <<= 1) {
            const bool dir = ((lane & k) == 0);
            #pragma unroll
            for (int j = k >> 1; j >= 1; j >>= 1) {
                bool lower = (lane & j) == 0;
                unsigned long long other = shflx64(key, j);
                key = cmpx(key, other, lower == dir);
            }
        }
        key = warp_merge_desc(key, lane);   // final k=32 pass, descending
        s[tid] = key;
    }
    __syncthreads();

    // ---- top-32 merge tree over nwarps sorted runs ----
    // Top-32 of two descending runs: max(a[lane], b[31-lane]) is bitonic,
    // cleaned by a 5-stage merge. Winner/partner slots are disjoint per step.
    for (int step = 1; step < nwarps; step <<= 1) {
        bool winner = ((wid & (2 * step - 1)) == 0) && (wid + step < nwarps);
        if (winner) {
            unsigned long long other = s[(wid + step) * 32 + (31 - lane)];
            key = key > other ? key : other;
            key = warp_merge_desc(key, lane);
            s[tid] = key;
        }
        __syncthreads();
    }

    // ---- warp 0 lane r holds rank-r key; publish indices ----
    const int kmax = min(K_TOP, size);
    if (wid == 0) {
        int lidx = (int)(~(unsigned int)(key & 0xFFFFFFFFull));
        tops[lane] = lidx;
        if (lane < K_TOP) {
            float idxval = (lane < kmax) ? (float)(offset + lidx) : -1.0f;
            __stcs(&out[(size_t)G * K_TOP * EMB_DIM + (size_t)g * K_TOP + lane],
                   idxval);
        }
    }
    __syncthreads();

    // ---- gather 30 rows x 128 f32: warp w owns rows {w, w+8, w+16, w+24} ----
    // All row indices read first, all LDG.128 issued back-to-back (MLP=4),
    // then stores. Rows >= kmax (never here, sizes >= 60) write zeros.
    {
        float4*       out4 = (float4*)(out + (size_t)g * K_TOP * EMB_DIM);
        const float4* emb4 = (const float4*)emb;
        const float4  zero = make_float4(0.f, 0.f, 0.f, 0.f);

        const int r0 = wid, r1 = wid + 8, r2 = wid + 16, r3 = wid + 24;
        const bool h3 = (r3 < K_TOP);           // warps 6,7 have only 3 rows

        int i0 = tops[r0], i1 = tops[r1], i2 = tops[r2];
        int i3 = h3 ? tops[r3] : 0;

        float4 v0 = (r0 < kmax) ? __ldg(&emb4[(size_t)(offset + i0) * 32 + lane]) : zero;
        float4 v1 = (r1 < kmax) ? __ldg(&emb4[(size_t)(offset + i1) * 32 + lane]) : zero;
        float4 v2 = (r2 < kmax) ? __ldg(&emb4[(size_t)(offset + i2) * 32 + lane]) : zero;
        float4 v3 = (h3 && r3 < kmax) ? __ldg(&emb4[(size_t)(offset + i3) * 32 + lane]) : zero;

        __stcs(&out4[r0 * 32 + lane], v0);
        __stcs(&out4[r1 * 32 + lane], v1);
        __stcs(&out4[r2 * 32 + lane], v2);
        if (h3) __stcs(&out4[r3 * 32 + lane], v3);
    }
}

extern "C" void kernel_launch(void* const* d_in, const int* in_sizes, int n_in,
                              void* d_out, int out_size) {
    const float* emb   = (const float*)d_in[0];
    const int*   sizes = (const int*)d_in[1];
    const int G = in_sizes[1];
    sortpool_kernel<<<G, NT>>>(emb, sizes, (float*)d_out, G);
}

// round 5
// speedup vs baseline: 1.0815x; 1.0815x over previous
#include <cuda_runtime.h>
#include <cstdint>

#define K_TOP    30
#define EMB_DIM  128
#define NT       128   // 4 warps per block -> 2048 blocks fit in ONE wave

// Map float -> uint32 whose unsigned order matches float order (ascending).
__device__ __forceinline__ unsigned int float_to_sortable(float f) {
    unsigned int b = __float_as_uint(f);
    return (b & 0x80000000u) ? ~b : (b | 0x80000000u);
}

__device__ __forceinline__ unsigned long long shflx64(unsigned long long x, int m) {
    unsigned lo = (unsigned)x, hi = (unsigned)(x >> 32);
    lo = __shfl_xor_sync(0xffffffffu, lo, m);
    hi = __shfl_xor_sync(0xffffffffu, hi, m);
    return ((unsigned long long)hi << 32) | lo;
}

__device__ __forceinline__ unsigned long long cmpx(unsigned long long a,
                                                   unsigned long long b,
                                                   bool keep_max) {
    unsigned long long mx = a > b ? a : b;
    unsigned long long mn = a > b ? b : a;
    return keep_max ? mx : mn;
}

// 5-stage descending bitonic merge (32-wide) of a bitonic sequence.
__device__ __forceinline__ unsigned long long warp_merge_desc(unsigned long long key,
                                                              int lane) {
    #pragma unroll
    for (int j = 16; j >= 1; j >>= 1) {
        bool lower = (lane & j) == 0;
        unsigned long long other = shflx64(key, j);
        key = cmpx(key, other, lower);
    }
    return key;
}

__global__ void __launch_bounds__(NT, 14)
sortpool_kernel(const float* __restrict__ emb,
                const int*   __restrict__ sizes,
                float*       __restrict__ out,
                int G) {
    const int g    = blockIdx.x;
    const int tid  = threadIdx.x;
    const int lane = tid & 31;
    const int wid  = tid >> 5;

    __shared__ unsigned long long s[NT];      // one 32-slot run per warp
    __shared__ int wsum[NT / 32];
    __shared__ int sh_off;
    __shared__ int tops[32];

    // ---- offset = prefix sum of sizes[0..g-1], int4-vectorized (L2-resident) ----
    int acc = 0;
    {
        const int4* s4 = (const int4*)sizes;
        const int nfull = g >> 2;
        for (int j = tid; j < nfull; j += NT) {
            int4 v = s4[j];
            acc += v.x + v.y + v.z + v.w;
        }
        if (tid < (g & 3)) acc += sizes[(nfull << 2) + tid];
    }
    #pragma unroll
    for (int m = 16; m; m >>= 1) acc += __shfl_xor_sync(0xffffffffu, acc, m);
    if (lane == 0) wsum[wid] = acc;
    __syncthreads();
    if (tid == 0) {
        int o = 0;
        #pragma unroll
        for (int w = 0; w < NT / 32; w++) o += wsum[w];
        sh_off = o;
    }
    __syncthreads();
    const int offset = sh_off;
    const int size   = sizes[g];
    const int nw64   = (size + 63) >> 6;   // warps holding data (64 elems each)

    // Composite keys: (sortable(val) << 32) | ~elem_idx. Descending composite
    // order == descending value, ascending index on ties. Lane holds elements
    // i0 = wid*64+lane (key0) and i1 = wid*64+32+lane (key1).
    const int i0 = (wid << 6) + lane;
    const int i1 = i0 + 32;
    unsigned long long key0 = (unsigned long long)(unsigned int)(~(unsigned int)i0);
    unsigned long long key1 = (unsigned long long)(unsigned int)(~(unsigned int)i1);

    if (wid < nw64) {
        if (i0 < size) {
            float v = __ldg(&emb[(size_t)(offset + i0) * EMB_DIM + (EMB_DIM - 1)]);
            key0 |= (unsigned long long)float_to_sortable(v) << 32;
        }
        if (i1 < size) {
            float v = __ldg(&emb[(size_t)(offset + i1) * EMB_DIM + (EMB_DIM - 1)]);
            key1 |= (unsigned long long)float_to_sortable(v) << 32;
        }

        // ---- 64-element bitonic sort (descending), 2 keys per lane ----
        // Element i<32 lives in key0[lane=i], i>=32 in key1[lane=i-32].
        // k = 2..16: both halves share dir = ((lane & k) == 0).
        #pragma unroll
        for (int k = 2; k <= 16; k <<= 1) {
            const bool dir = ((lane & k) == 0);
            #pragma unroll
            for (int j = k >> 1; j >= 1; j >>= 1) {
                bool lower = (lane & j) == 0;
                key0 = cmpx(key0, shflx64(key0, j), lower == dir);
                key1 = cmpx(key1, shflx64(key1, j), lower == dir);
            }
        }
        // k = 32: key0 half descending, key1 half ascending.
        {
            #pragma unroll
            for (int j = 16; j >= 1; j >>= 1) {
                bool lower = (lane & j) == 0;
                key0 = cmpx(key0, shflx64(key0, j), lower);
                key1 = cmpx(key1, shflx64(key1, j), !lower);
            }
        }
        // k = 64: j=32 is intra-thread (max stays in low half), then 5-stage
        // descending merges on each half.
        {
            unsigned long long mx = key0 > key1 ? key0 : key1;
            unsigned long long mn = key0 > key1 ? key1 : key0;
            key0 = mx; key1 = mn;
            key0 = warp_merge_desc(key0, lane);
            key1 = warp_merge_desc(key1, lane);
        }
        // Warp's top-32 (ranks 0..31 of its 64) now in key0, descending.
        s[(wid << 5) + lane] = key0;
    }
    __syncthreads();

    // ---- top-32 merge tree over nw64 sorted runs ----
    // Top-32 of two descending runs: max(a[lane], b[31-lane]) is bitonic,
    // cleaned by a 5-stage merge. Winner/partner slots are disjoint per step.
    for (int step = 1; step < nw64; step <<= 1) {
        bool winner = ((wid & (2 * step - 1)) == 0) && (wid + step < nw64);
        if (winner) {
            unsigned long long other = s[((wid + step) << 5) + (31 - lane)];
            key0 = key0 > other ? key0 : other;
            key0 = warp_merge_desc(key0, lane);
            s[(wid << 5) + lane] = key0;
        }
        __syncthreads();
    }

    // ---- warp 0 lane r holds rank-r key; publish indices ----
    const int kmax = min(K_TOP, size);
    if (wid == 0) {
        int lidx = (int)(~(unsigned int)(key0 & 0xFFFFFFFFull));
        tops[lane] = lidx;
        if (lane < K_TOP) {
            float idxval = (lane < kmax) ? (float)(offset + lidx) : -1.0f;
            __stcs(&out[(size_t)G * K_TOP * EMB_DIM + (size_t)g * K_TOP + lane],
                   idxval);
        }
    }
    __syncthreads();

    // ---- gather 30 rows x 128 f32: warp w owns rows w, w+4, ..., w+28 ----
    // Two batches of 4 rows, LDG.128s issued back-to-back (MLP=4 per batch),
    // bounded register footprint for 14 CTAs/SM.
    {
        float4*       out4 = (float4*)(out + (size_t)g * K_TOP * EMB_DIM);
        const float4* emb4 = (const float4*)emb;
        const float4  zero = make_float4(0.f, 0.f, 0.f, 0.f);

        #pragma unroll
        for (int base = 0; base < 2; base++) {
            const int r0 = wid + (base * 4 + 0) * 4;
            const int r1 = wid + (base * 4 + 1) * 4;
            const int r2 = wid + (base * 4 + 2) * 4;
            const int r3 = wid + (base * 4 + 3) * 4;
            const bool h3 = (r3 < K_TOP);

            int a0 = tops[r0], a1 = tops[r1], a2 = tops[r2];
            int a3 = h3 ? tops[r3] : 0;

            float4 v0 = (r0 < kmax) ? __ldg(&emb4[(size_t)(offset + a0) * 32 + lane]) : zero;
            float4 v1 = (r1 < kmax) ? __ldg(&emb4[(size_t)(offset + a1) * 32 + lane]) : zero;
            float4 v2 = (r2 < kmax) ? __ldg(&emb4[(size_t)(offset + a2) * 32 + lane]) : zero;
            float4 v3 = (h3 && r3 < kmax) ? __ldg(&emb4[(size_t)(offset + a3) * 32 + lane]) : zero;

            __stcs(&out4[r0 * 32 + lane], v0);
            __stcs(&out4[r1 * 32 + lane], v1);
            __stcs(&out4[r2 * 32 + lane], v2);
            if (h3) __stcs(&out4[r3 * 32 + lane], v3);
        }
    }
}

extern "C" void kernel_launch(void* const* d_in, const int* in_sizes, int n_in,
                              void* d_out, int out_size) {
    const float* emb   = (const float*)d_in[0];
    const int*   sizes = (const int*)d_in[1];
    const int G = in_sizes[1];
    sortpool_kernel<<<G, NT>>>(emb, sizes, (float*)d_out, G);
}